// round 8
// baseline (speedup 1.0000x reference)
#include <cuda_runtime.h>
#include <math.h>

#define Bsz 1024
#define INd 256
#define Hd  512
#define Pd  128

// ---------------- scratch (no allocations allowed) ----------------
__device__ float g_h0[Bsz * Hd];
__device__ float g_h1[Bsz * Hd];
__device__ float g_q [Bsz * Hd];   // reused: split-K partials (f1/lin0 p0, fea 4xB*P)
__device__ float g_k [Bsz * Hd];   // reused: split-K partial p1
__device__ float g_v [Bsz * Hd];

// ---------------- helpers ----------------
__device__ __forceinline__ float ex2f(float x) {
    float y;
    asm("ex2.approx.f32 %0, %1;" : "=f"(y) : "f"(x));
    return y;
}

// packed fp32x2 FMA (FFMA2): 2 exact fp32 FMAs per instruction
#define FMA2(c, a, b) \
    asm("fma.rn.f32x2 %0, %1, %2, %0;" : "+l"(c) : "l"(a), "l"(b))
#define PACK2(d, s) \
    asm("mov.b64 %0, {%1, %1};" : "=l"(d) : "f"(s))
#define UNPACK2(lo, hi, s) \
    asm("mov.b64 {%0, %1}, %2;" : "=f"(lo), "=f"(hi) : "l"(s))

// ---------------- GEMM: C[M,N] = A[M,K] @ W[N,K]^T ----------------
// MODE 0: +bias epilogue; blockIdx.z selects (W,bias,C) triple (qkv fusion)
// MODE 2: split-K; blockIdx.z = k-chunk; no bias; C = C[z] (partials)
struct GemmArgs {
    const float* A;
    const float* W[4];
    const float* bias[4];
    float*       C[4];
    int M, N, K;
};

constexpr int BM = 64, BN = 64, BK = 16;

template <int MODE, int SPLIT>
__global__ __launch_bounds__(128) void gemm_kernel(GemmArgs g) {
    const int z = blockIdx.z;
    const float* __restrict__ A = g.A;
    const float* __restrict__ W = (MODE == 0) ? g.W[z] : g.W[0];
    float* __restrict__ C       = g.C[z];
    const int N = g.N, K = g.K;
    const int kloc = K / SPLIT;
    const int kbeg = (MODE == 2) ? z * kloc : 0;

    __shared__ float As[2][BK][BM + 4];
    __shared__ float Ws[2][BK][BN + 4];

    const int tid = threadIdx.x;
    const int tx = tid & 7;         // n-dir: 8 cols -> 8 floats each = 64
    const int ty = tid >> 3;        // m-dir: 16 rows -> 4 each = 64
    const int m0 = blockIdx.y * BM;
    const int n0 = blockIdx.x * BN;

    const int lr = tid >> 1;        // fill row 0..63
    const int lk = (tid & 1) * 8;   // fill k half: 0 or 8

    unsigned long long acc[4][4];   // 4 m-rows x 4 f32x2 n-pairs = 4x8 fp32
#pragma unroll
    for (int i = 0; i < 4; i++)
#pragma unroll
        for (int p = 0; p < 4; p++) acc[i][p] = 0ULL;

    const float* Ap = &A[(m0 + lr) * K + kbeg + lk];
    const float* Wp = &W[(n0 + lr) * K + kbeg + lk];

    const int nstage = kloc / BK;

    float4 av0 = *(const float4*)Ap;
    float4 av1 = *(const float4*)(Ap + 4);
    float4 wv0 = *(const float4*)Wp;
    float4 wv1 = *(const float4*)(Wp + 4);

#define STORE_STAGE(bf)                                                    \
    do {                                                                   \
        As[bf][lk + 0][lr] = av0.x; As[bf][lk + 1][lr] = av0.y;            \
        As[bf][lk + 2][lr] = av0.z; As[bf][lk + 3][lr] = av0.w;            \
        As[bf][lk + 4][lr] = av1.x; As[bf][lk + 5][lr] = av1.y;            \
        As[bf][lk + 6][lr] = av1.z; As[bf][lk + 7][lr] = av1.w;            \
        Ws[bf][lk + 0][lr] = wv0.x; Ws[bf][lk + 1][lr] = wv0.y;            \
        Ws[bf][lk + 2][lr] = wv0.z; Ws[bf][lk + 3][lr] = wv0.w;            \
        Ws[bf][lk + 4][lr] = wv1.x; Ws[bf][lk + 5][lr] = wv1.y;            \
        Ws[bf][lk + 6][lr] = wv1.z; Ws[bf][lk + 7][lr] = wv1.w;            \
    } while (0)

    STORE_STAGE(0);
    __syncthreads();

    for (int s = 0; s < nstage; s++) {
        const int buf = s & 1;
        if (s + 1 < nstage) {                 // global prefetch for next stage
            av0 = *(const float4*)(Ap + (s + 1) * BK);
            av1 = *(const float4*)(Ap + (s + 1) * BK + 4);
            wv0 = *(const float4*)(Wp + (s + 1) * BK);
            wv1 = *(const float4*)(Wp + (s + 1) * BK + 4);
        }

        const float* sA = &As[buf][0][ty * 4];
        const float* sW = &Ws[buf][0][tx * 8];
        float4     a_cur  = *(const float4*)sA;
        ulonglong2 b0_cur = *(const ulonglong2*)sW;
        ulonglong2 b1_cur = *(const ulonglong2*)(sW + 4);
#pragma unroll
        for (int kk = 0; kk < BK; kk++) {
            const int kn = (kk + 1 < BK) ? kk + 1 : kk;   // reg prefetch dist 1
            float4     a_nxt  = *(const float4*)(sA + kn * (BM + 4));
            ulonglong2 b0_nxt = *(const ulonglong2*)(sW + kn * (BN + 4));
            ulonglong2 b1_nxt = *(const ulonglong2*)(sW + kn * (BN + 4) + 4);
            unsigned long long aa0, aa1, aa2, aa3;
            PACK2(aa0, a_cur.x); PACK2(aa1, a_cur.y);
            PACK2(aa2, a_cur.z); PACK2(aa3, a_cur.w);
            FMA2(acc[0][0], aa0, b0_cur.x); FMA2(acc[0][1], aa0, b0_cur.y);
            FMA2(acc[0][2], aa0, b1_cur.x); FMA2(acc[0][3], aa0, b1_cur.y);
            FMA2(acc[1][0], aa1, b0_cur.x); FMA2(acc[1][1], aa1, b0_cur.y);
            FMA2(acc[1][2], aa1, b1_cur.x); FMA2(acc[1][3], aa1, b1_cur.y);
            FMA2(acc[2][0], aa2, b0_cur.x); FMA2(acc[2][1], aa2, b0_cur.y);
            FMA2(acc[2][2], aa2, b1_cur.x); FMA2(acc[2][3], aa2, b1_cur.y);
            FMA2(acc[3][0], aa3, b0_cur.x); FMA2(acc[3][1], aa3, b0_cur.y);
            FMA2(acc[3][2], aa3, b1_cur.x); FMA2(acc[3][3], aa3, b1_cur.y);
            a_cur = a_nxt; b0_cur = b0_nxt; b1_cur = b1_nxt;
        }

        if (s + 1 < nstage) {
            __syncthreads();          // everyone done reading buf^1's old data
            STORE_STAGE(buf ^ 1);
            __syncthreads();
        }
    }
#undef STORE_STAGE

    const int nc = n0 + tx * 8;
    float4 bv0, bv1;
    if (MODE == 0) {
        const float* __restrict__ bias = g.bias[z];
        bv0 = *(const float4*)&bias[nc];
        bv1 = *(const float4*)&bias[nc + 4];
    } else {
        bv0 = make_float4(0.f, 0.f, 0.f, 0.f);
        bv1 = bv0;
    }
#pragma unroll
    for (int i = 0; i < 4; i++) {
        const int m = m0 + ty * 4 + i;
        float4 o0, o1;
        UNPACK2(o0.x, o0.y, acc[i][0]);
        UNPACK2(o0.z, o0.w, acc[i][1]);
        UNPACK2(o1.x, o1.y, acc[i][2]);
        UNPACK2(o1.z, o1.w, acc[i][3]);
        o0.x += bv0.x; o0.y += bv0.y; o0.z += bv0.z; o0.w += bv0.w;
        o1.x += bv1.x; o1.y += bv1.y; o1.z += bv1.z; o1.w += bv1.w;
        *(float4*)&C[m * N + nc]     = o0;
        *(float4*)&C[m * N + nc + 4] = o1;
    }
}

// ---------------- split-K reduce epilogues ----------------
// out = p0 + p1 + bias      (lin0)
__global__ __launch_bounds__(256) void reduce_bias_kernel(const float* __restrict__ p0,
                                                          const float* __restrict__ p1,
                                                          const float* __restrict__ bias,
                                                          float* __restrict__ out) {
    const int i = blockIdx.x * 256 + threadIdx.x;       // float4 index
    const int col = (i * 4) & (Hd - 1);
    float4 a = ((const float4*)p0)[i];
    float4 b = ((const float4*)p1)[i];
    float4 c = *(const float4*)&bias[col];
    float4 o = make_float4(a.x + b.x + c.x, a.y + b.y + c.y,
                           a.z + b.z + c.z, a.w + b.w + c.w);
    ((float4*)out)[i] = o;
}

// out = res + gelu_exact(p0 + p1 + bias)      (f1)
__global__ __launch_bounds__(256) void reduce_gelu_kernel(const float* __restrict__ p0,
                                                          const float* __restrict__ p1,
                                                          const float* __restrict__ bias,
                                                          const float* __restrict__ res,
                                                          float* __restrict__ out) {
    const int i = blockIdx.x * 256 + threadIdx.x;
    const int col = (i * 4) & (Hd - 1);
    float4 a = ((const float4*)p0)[i];
    float4 b = ((const float4*)p1)[i];
    float4 c = *(const float4*)&bias[col];
    float4 r = ((const float4*)res)[i];
    float4 o;
    float s;
    s = a.x + b.x + c.x; o.x = r.x + 0.5f * s * (1.0f + erff(s * 0.70710678118654752f));
    s = a.y + b.y + c.y; o.y = r.y + 0.5f * s * (1.0f + erff(s * 0.70710678118654752f));
    s = a.z + b.z + c.z; o.z = r.z + 0.5f * s * (1.0f + erff(s * 0.70710678118654752f));
    s = a.w + b.w + c.w; o.w = r.w + 0.5f * s * (1.0f + erff(s * 0.70710678118654752f));
    ((float4*)out)[i] = o;
}

// ---------------- attention: h[b,i] += sum_j softmax_j(q_i k_j) v_j ----------------
__global__ __launch_bounds__(256) void attn_kernel(const float* __restrict__ q,
                                                   const float* __restrict__ k,
                                                   const float* __restrict__ v,
                                                   float* __restrict__ h) {
    const int b = blockIdx.x;
    __shared__ float k2s[Hd];
    __shared__ float vs[Hd];
    __shared__ float redmax[256];
    __shared__ float redmin[256];
    const int tid = threadIdx.x;
    const float LOG2E = 1.4426950408889634f;

    float lmax = -1e30f, lmin = 1e30f;
#pragma unroll
    for (int ii = 0; ii < Hd / 256; ii++) {
        int j = tid + ii * 256;
        float kk = k[b * Hd + j] * LOG2E;   // pre-scale: exp(x) = 2^(x*log2e)
        k2s[j] = kk;
        vs[j]  = v[b * Hd + j];
        lmax = fmaxf(lmax, kk);
        lmin = fminf(lmin, kk);
    }
    redmax[tid] = lmax;
    redmin[tid] = lmin;
    __syncthreads();
    for (int s = 128; s > 0; s >>= 1) {
        if (tid < s) {
            redmax[tid] = fmaxf(redmax[tid], redmax[tid + s]);
            redmin[tid] = fminf(redmin[tid], redmin[tid + s]);
        }
        __syncthreads();
    }
    const float kmax = redmax[0], kmin = redmin[0];

    const float q0 = q[b * Hd + tid];
    const float q1 = q[b * Hd + tid + 256];
    const float m0 = (q0 >= 0.f) ? q0 * kmax : q0 * kmin;  // max_j q*k (log2 domain)
    const float m1 = (q1 >= 0.f) ? q1 * kmax : q1 * kmin;

    float d0 = 0.f, d1 = 0.f, n0 = 0.f, n1 = 0.f;
#pragma unroll 8
    for (int j = 0; j < Hd; j++) {
        float kv = k2s[j];
        float vv = vs[j];
        float e0 = ex2f(fmaf(q0, kv, -m0));
        float e1 = ex2f(fmaf(q1, kv, -m1));
        d0 += e0;
        d1 += e1;
        n0 = fmaf(e0, vv, n0);
        n1 = fmaf(e1, vv, n1);
    }
    h[b * Hd + tid]       += n0 / d0;
    h[b * Hd + tid + 256] += n1 / d1;
}

// ---------------- fea split-K reduce + bias + reg head ----------------
__global__ __launch_bounds__(128) void fea_reg_kernel(const float* __restrict__ part,
                                                      const float* __restrict__ fea_b,
                                                      const float* __restrict__ reg_w,
                                                      const float* __restrict__ reg_b,
                                                      float* __restrict__ out_fea,
                                                      float* __restrict__ out_scalar) {
    const int b = blockIdx.x;
    const int p = threadIdx.x;
    const int idx = b * Pd + p;
    float s = part[idx]
            + part[Bsz * Pd + idx]
            + part[2 * Bsz * Pd + idx]
            + part[3 * Bsz * Pd + idx]
            + fea_b[p];
    out_fea[idx] = s;

    float d = s * reg_w[p];
#pragma unroll
    for (int o = 16; o; o >>= 1) d += __shfl_xor_sync(0xffffffffu, d, o);
    __shared__ float ws[4];
    if ((p & 31) == 0) ws[p >> 5] = d;
    __syncthreads();
    if (p == 0) out_scalar[b] = ws[0] + ws[1] + ws[2] + ws[3] + reg_b[0];
}

// ---------------- launcher ----------------
extern "C" void kernel_launch(void* const* d_in, const int* in_sizes, int n_in,
                              void* d_out, int out_size) {
    const float* x      = (const float*)d_in[0];
    const float* lin0_w = (const float*)d_in[1];
    const float* lin0_b = (const float*)d_in[2];
    const float* b1_qw = (const float*)d_in[3];  const float* b1_qb = (const float*)d_in[4];
    const float* b1_kw = (const float*)d_in[5];  const float* b1_kb = (const float*)d_in[6];
    const float* b1_vw = (const float*)d_in[7];  const float* b1_vb = (const float*)d_in[8];
    const float* b1_f1w = (const float*)d_in[9]; const float* b1_f1b = (const float*)d_in[10];
    const float* b2_qw = (const float*)d_in[11]; const float* b2_qb = (const float*)d_in[12];
    const float* b2_kw = (const float*)d_in[13]; const float* b2_kb = (const float*)d_in[14];
    const float* b2_vw = (const float*)d_in[15]; const float* b2_vb = (const float*)d_in[16];
    const float* b2_f1w = (const float*)d_in[17]; const float* b2_f1b = (const float*)d_in[18];
    const float* fea_w = (const float*)d_in[19]; const float* fea_b = (const float*)d_in[20];
    const float* reg_w = (const float*)d_in[21]; const float* reg_b = (const float*)d_in[22];

    float* out_scalar = (float*)d_out;           // [B]
    float* out_fea    = (float*)d_out + Bsz;     // [B, P]

    float *h0, *h1, *qb, *kb, *vb;
    cudaGetSymbolAddress((void**)&h0, g_h0);
    cudaGetSymbolAddress((void**)&h1, g_h1);
    cudaGetSymbolAddress((void**)&qb, g_q);
    cudaGetSymbolAddress((void**)&kb, g_k);
    cudaGetSymbolAddress((void**)&vb, g_v);

    const dim3 blk(128);
    const int RED_BLOCKS = (Bsz * Hd / 4) / 256;   // 512

    // 1) lin0: split-K=2 -> partials in qb/kb, then reduce+bias -> h0
    {
        GemmArgs a{};
        a.A = x; a.W[0] = lin0_w; a.C[0] = qb; a.C[1] = kb;
        a.M = Bsz; a.N = Hd; a.K = INd;
        gemm_kernel<2, 2><<<dim3(Hd / BN, Bsz / BM, 2), blk>>>(a);
        reduce_bias_kernel<<<RED_BLOCKS, 256>>>(qb, kb, lin0_b, h0);
    }

    // ---- block 1 (h0 -> h1) ----
    {
        GemmArgs a{};
        a.A = h0;
        a.W[0] = b1_qw; a.W[1] = b1_kw; a.W[2] = b1_vw;
        a.bias[0] = b1_qb; a.bias[1] = b1_kb; a.bias[2] = b1_vb;
        a.C[0] = qb; a.C[1] = kb; a.C[2] = vb;
        a.M = Bsz; a.N = Hd; a.K = Hd;
        gemm_kernel<0, 1><<<dim3(Hd / BN, Bsz / BM, 3), blk>>>(a);
    }
    attn_kernel<<<Bsz, 256>>>(qb, kb, vb, h0);
    {
        GemmArgs a{};
        a.A = h0; a.W[0] = b1_f1w; a.C[0] = qb; a.C[1] = kb;
        a.M = Bsz; a.N = Hd; a.K = Hd;
        gemm_kernel<2, 2><<<dim3(Hd / BN, Bsz / BM, 2), blk>>>(a);
        reduce_gelu_kernel<<<RED_BLOCKS, 256>>>(qb, kb, b1_f1b, h0, h1);
    }

    // ---- block 2 (h1 -> h0) ----
    {
        GemmArgs a{};
        a.A = h1;
        a.W[0] = b2_qw; a.W[1] = b2_kw; a.W[2] = b2_vw;
        a.bias[0] = b2_qb; a.bias[1] = b2_kb; a.bias[2] = b2_vb;
        a.C[0] = qb; a.C[1] = kb; a.C[2] = vb;
        a.M = Bsz; a.N = Hd; a.K = Hd;
        gemm_kernel<0, 1><<<dim3(Hd / BN, Bsz / BM, 3), blk>>>(a);
    }
    attn_kernel<<<Bsz, 256>>>(qb, kb, vb, h1);
    {
        GemmArgs a{};
        a.A = h1; a.W[0] = b2_f1w; a.C[0] = qb; a.C[1] = kb;
        a.M = Bsz; a.N = Hd; a.K = Hd;
        gemm_kernel<2, 2><<<dim3(Hd / BN, Bsz / BM, 2), blk>>>(a);
        reduce_gelu_kernel<<<RED_BLOCKS, 256>>>(qb, kb, b2_f1b, h1, h0);
    }

    // 4) fea: split-K=4, partials packed in g_q
    {
        GemmArgs a{};
        a.A = h0; a.W[0] = fea_w;
        a.C[0] = qb;
        a.C[1] = qb + Bsz * Pd;
        a.C[2] = qb + 2 * Bsz * Pd;
        a.C[3] = qb + 3 * Bsz * Pd;
        a.M = Bsz; a.N = Pd; a.K = Hd;
        gemm_kernel<2, 4><<<dim3(Pd / BN, Bsz / BM, 4), blk>>>(a);
    }

    // 5) reduce partials + bias -> fea (d_out), then out[b] = fea·reg_w + reg_b
    fea_reg_kernel<<<Bsz, 128>>>(qb, fea_b, reg_w, reg_b, out_fea, out_scalar);
}

// round 9
// speedup vs baseline: 1.2398x; 1.2398x over previous
#include <cuda_runtime.h>
#include <math.h>

#define Bsz 1024
#define INd 256
#define Hd  512
#define Pd  128

// ---------------- scratch (no allocations allowed) ----------------
__device__ float g_h0[Bsz * Hd];
__device__ float g_h1[Bsz * Hd];
__device__ float g_q [Bsz * Hd];   // reused as split-K partial p0 / fea partials
__device__ float g_k [Bsz * Hd];   // reused as split-K partial p1
__device__ float g_v [Bsz * Hd];

// ---------------- helpers ----------------
__device__ __forceinline__ float ex2f(float x) {
    float y;
    asm("ex2.approx.f32 %0, %1;" : "=f"(y) : "f"(x));
    return y;
}

// packed fp32x2 FMA (FFMA2): 2 exact fp32 FMAs per instruction
#define FMA2(c, a, b) \
    asm("fma.rn.f32x2 %0, %1, %2, %0;" : "+l"(c) : "l"(a), "l"(b))
#define PACK2(d, s) \
    asm("mov.b64 %0, {%1, %1};" : "=l"(d) : "f"(s))
#define UNPACK2(lo, hi, s) \
    asm("mov.b64 {%0, %1}, %2;" : "=f"(lo), "=f"(hi) : "l"(s))

// ---------------- GEMM: C[M,N] = A[M,K] @ W[N,K]^T ----------------
// MODE 0: +bias epilogue; blockIdx.z selects (W,bias,C) triple (qkv fusion)
// MODE 2: split-K; blockIdx.z = k-chunk z; raw partials to C[z], no bias
struct GemmArgs {
    const float* A;
    const float* W[4];
    const float* bias[4];
    float*       C[4];
    int M, N, K;
};

constexpr int BM = 64, BN = 64, BK = 16;

template <int MODE, int SPLIT>
__global__ __launch_bounds__(256) void gemm_kernel(GemmArgs g) {
    const int z = blockIdx.z;
    const float* __restrict__ A = g.A;
    const float* __restrict__ W = (MODE == 0) ? g.W[z] : g.W[0];
    float* __restrict__ C       = g.C[z];
    const int N = g.N, K = g.K;
    const int kloc = K / SPLIT;
    const int kbeg = (MODE == 2) ? z * kloc : 0;

    __shared__ float As[2][BK][BM + 4];
    __shared__ float Ws[2][BK][BN + 4];

    const int tid = threadIdx.x;
    const int tx = tid & 15;        // n-dir (4 floats = 2 f32x2 pairs)
    const int ty = tid >> 4;        // m-dir
    const int m0 = blockIdx.y * BM;
    const int n0 = blockIdx.x * BN;

    const int lr = tid >> 2;        // 0..63 : row within tile
    const int lk = (tid & 3) * 4;   // 0,4,8,12 : k offset

    unsigned long long acc[4][2];   // 4 m-rows x 2 f32x2 n-pairs = 4x4 fp32
#pragma unroll
    for (int i = 0; i < 4; i++) { acc[i][0] = 0ULL; acc[i][1] = 0ULL; }

    const float* Ap = &A[(m0 + lr) * K + kbeg + lk];
    const float* Wp = &W[(n0 + lr) * K + kbeg + lk];

    const int nstage = kloc / BK;

    // stage 0: global -> smem
    float4 av = *(const float4*)Ap;
    float4 wv = *(const float4*)Wp;
    As[0][lk + 0][lr] = av.x; As[0][lk + 1][lr] = av.y;
    As[0][lk + 2][lr] = av.z; As[0][lk + 3][lr] = av.w;
    Ws[0][lk + 0][lr] = wv.x; Ws[0][lk + 1][lr] = wv.y;
    Ws[0][lk + 2][lr] = wv.z; Ws[0][lk + 3][lr] = wv.w;
    __syncthreads();

    for (int s = 0; s < nstage; s++) {
        const int buf = s & 1;
        // prefetch next stage's global data into registers (hidden under compute)
        if (s + 1 < nstage) {
            av = *(const float4*)(Ap + (s + 1) * BK);
            wv = *(const float4*)(Wp + (s + 1) * BK);
        }

        const float* sA = &As[buf][0][ty * 4];
        const float* sW = &Ws[buf][0][tx * 4];
        float4     a_cur = *(const float4*)sA;
        ulonglong2 b_cur = *(const ulonglong2*)sW;   // 4 fp32 = 2 f32x2 pairs
#pragma unroll
        for (int kk = 0; kk < BK; kk++) {
            const int kn = (kk + 1 < BK) ? kk + 1 : kk;   // register prefetch, distance 1
            float4     a_nxt = *(const float4*)(sA + kn * (BM + 4));
            ulonglong2 b_nxt = *(const ulonglong2*)(sW + kn * (BN + 4));
            unsigned long long aa0, aa1, aa2, aa3;
            PACK2(aa0, a_cur.x); PACK2(aa1, a_cur.y);
            PACK2(aa2, a_cur.z); PACK2(aa3, a_cur.w);
            FMA2(acc[0][0], aa0, b_cur.x); FMA2(acc[0][1], aa0, b_cur.y);
            FMA2(acc[1][0], aa1, b_cur.x); FMA2(acc[1][1], aa1, b_cur.y);
            FMA2(acc[2][0], aa2, b_cur.x); FMA2(acc[2][1], aa2, b_cur.y);
            FMA2(acc[3][0], aa3, b_cur.x); FMA2(acc[3][1], aa3, b_cur.y);
            a_cur = a_nxt; b_cur = b_nxt;
        }

        if (s + 1 < nstage) {
            const int nb = buf ^ 1;
            As[nb][lk + 0][lr] = av.x; As[nb][lk + 1][lr] = av.y;
            As[nb][lk + 2][lr] = av.z; As[nb][lk + 3][lr] = av.w;
            Ws[nb][lk + 0][lr] = wv.x; Ws[nb][lk + 1][lr] = wv.y;
            Ws[nb][lk + 2][lr] = wv.z; Ws[nb][lk + 3][lr] = wv.w;
            __syncthreads();
        }
    }

    const int nc = n0 + tx * 4;
    float4 bv;
    if (MODE == 2) bv = make_float4(0.f, 0.f, 0.f, 0.f);
    else           bv = *(const float4*)&g.bias[z][nc];
#pragma unroll
    for (int i = 0; i < 4; i++) {
        const int m = m0 + ty * 4 + i;
        float4 o;
        UNPACK2(o.x, o.y, acc[i][0]);
        UNPACK2(o.z, o.w, acc[i][1]);
        o.x += bv.x; o.y += bv.y; o.z += bv.z; o.w += bv.w;
        *(float4*)&C[m * N + nc] = o;
    }
}

// ---------------- split-K reduce epilogues ----------------
// out = p0 + p1 + bias      (lin0)
__global__ __launch_bounds__(256) void reduce_bias_kernel(const float* __restrict__ p0,
                                                          const float* __restrict__ p1,
                                                          const float* __restrict__ bias,
                                                          float* __restrict__ out) {
    const int i = blockIdx.x * 256 + threadIdx.x;       // float4 index
    const int col = (i * 4) & (Hd - 1);
    float4 a = ((const float4*)p0)[i];
    float4 b = ((const float4*)p1)[i];
    float4 c = *(const float4*)&bias[col];
    float4 o = make_float4(a.x + b.x + c.x, a.y + b.y + c.y,
                           a.z + b.z + c.z, a.w + b.w + c.w);
    ((float4*)out)[i] = o;
}

// out = res + gelu_exact(p0 + p1 + bias)      (f1)
__global__ __launch_bounds__(256) void reduce_gelu_kernel(const float* __restrict__ p0,
                                                          const float* __restrict__ p1,
                                                          const float* __restrict__ bias,
                                                          const float* __restrict__ res,
                                                          float* __restrict__ out) {
    const int i = blockIdx.x * 256 + threadIdx.x;
    const int col = (i * 4) & (Hd - 1);
    float4 a = ((const float4*)p0)[i];
    float4 b = ((const float4*)p1)[i];
    float4 c = *(const float4*)&bias[col];
    float4 r = ((const float4*)res)[i];
    float4 o;
    float s;
    s = a.x + b.x + c.x; o.x = r.x + 0.5f * s * (1.0f + erff(s * 0.70710678118654752f));
    s = a.y + b.y + c.y; o.y = r.y + 0.5f * s * (1.0f + erff(s * 0.70710678118654752f));
    s = a.z + b.z + c.z; o.z = r.z + 0.5f * s * (1.0f + erff(s * 0.70710678118654752f));
    s = a.w + b.w + c.w; o.w = r.w + 0.5f * s * (1.0f + erff(s * 0.70710678118654752f));
    ((float4*)out)[i] = o;
}

// ---------------- attention: h[b,i] += sum_j softmax_j(q_i k_j) v_j ----------------
// At the MUFU floor (1 ex2 per (i,j); 16 lanes/cyc/SM) — do not touch.
__global__ __launch_bounds__(256) void attn_kernel(const float* __restrict__ q,
                                                   const float* __restrict__ k,
                                                   const float* __restrict__ v,
                                                   float* __restrict__ h) {
    const int b = blockIdx.x;
    __shared__ float k2s[Hd];
    __shared__ float vs[Hd];
    __shared__ float redmax[256];
    __shared__ float redmin[256];
    const int tid = threadIdx.x;
    const float LOG2E = 1.4426950408889634f;

    float lmax = -1e30f, lmin = 1e30f;
#pragma unroll
    for (int ii = 0; ii < Hd / 256; ii++) {
        int j = tid + ii * 256;
        float kk = k[b * Hd + j] * LOG2E;   // pre-scale: exp(x) = 2^(x*log2e)
        k2s[j] = kk;
        vs[j]  = v[b * Hd + j];
        lmax = fmaxf(lmax, kk);
        lmin = fminf(lmin, kk);
    }
    redmax[tid] = lmax;
    redmin[tid] = lmin;
    __syncthreads();
    for (int s = 128; s > 0; s >>= 1) {
        if (tid < s) {
            redmax[tid] = fmaxf(redmax[tid], redmax[tid + s]);
            redmin[tid] = fminf(redmin[tid], redmin[tid + s]);
        }
        __syncthreads();
    }
    const float kmax = redmax[0], kmin = redmin[0];

    const float q0 = q[b * Hd + tid];
    const float q1 = q[b * Hd + tid + 256];
    const float m0 = (q0 >= 0.f) ? q0 * kmax : q0 * kmin;  // max_j q*k (log2 domain)
    const float m1 = (q1 >= 0.f) ? q1 * kmax : q1 * kmin;

    float d0 = 0.f, d1 = 0.f, n0 = 0.f, n1 = 0.f;
#pragma unroll 8
    for (int j = 0; j < Hd; j++) {
        float kv = k2s[j];
        float vv = vs[j];
        float e0 = ex2f(fmaf(q0, kv, -m0));
        float e1 = ex2f(fmaf(q1, kv, -m1));
        d0 += e0;
        d1 += e1;
        n0 = fmaf(e0, vv, n0);
        n1 = fmaf(e1, vv, n1);
    }
    h[b * Hd + tid]       += n0 / d0;
    h[b * Hd + tid + 256] += n1 / d1;
}

// ---------------- fea split-K reduce + bias + reg head ----------------
__global__ __launch_bounds__(128) void fea_reg_kernel(const float* __restrict__ part,
                                                      const float* __restrict__ fea_b,
                                                      const float* __restrict__ reg_w,
                                                      const float* __restrict__ reg_b,
                                                      float* __restrict__ out_fea,
                                                      float* __restrict__ out_scalar) {
    const int b = blockIdx.x;
    const int p = threadIdx.x;
    const int idx = b * Pd + p;
    float s = part[idx]
            + part[Bsz * Pd + idx]
            + part[2 * Bsz * Pd + idx]
            + part[3 * Bsz * Pd + idx]
            + fea_b[p];
    out_fea[idx] = s;

    float d = s * reg_w[p];
#pragma unroll
    for (int o = 16; o; o >>= 1) d += __shfl_xor_sync(0xffffffffu, d, o);
    __shared__ float ws[4];
    if ((p & 31) == 0) ws[p >> 5] = d;
    __syncthreads();
    if (p == 0) out_scalar[b] = ws[0] + ws[1] + ws[2] + ws[3] + reg_b[0];
}

// ---------------- launcher ----------------
extern "C" void kernel_launch(void* const* d_in, const int* in_sizes, int n_in,
                              void* d_out, int out_size) {
    const float* x      = (const float*)d_in[0];
    const float* lin0_w = (const float*)d_in[1];
    const float* lin0_b = (const float*)d_in[2];
    const float* b1_qw = (const float*)d_in[3];  const float* b1_qb = (const float*)d_in[4];
    const float* b1_kw = (const float*)d_in[5];  const float* b1_kb = (const float*)d_in[6];
    const float* b1_vw = (const float*)d_in[7];  const float* b1_vb = (const float*)d_in[8];
    const float* b1_f1w = (const float*)d_in[9]; const float* b1_f1b = (const float*)d_in[10];
    const float* b2_qw = (const float*)d_in[11]; const float* b2_qb = (const float*)d_in[12];
    const float* b2_kw = (const float*)d_in[13]; const float* b2_kb = (const float*)d_in[14];
    const float* b2_vw = (const float*)d_in[15]; const float* b2_vb = (const float*)d_in[16];
    const float* b2_f1w = (const float*)d_in[17]; const float* b2_f1b = (const float*)d_in[18];
    const float* fea_w = (const float*)d_in[19]; const float* fea_b = (const float*)d_in[20];
    const float* reg_w = (const float*)d_in[21]; const float* reg_b = (const float*)d_in[22];

    float* out_scalar = (float*)d_out;           // [B]
    float* out_fea    = (float*)d_out + Bsz;     // [B, P]

    float *h0, *h1, *qb, *kb, *vb;
    cudaGetSymbolAddress((void**)&h0, g_h0);
    cudaGetSymbolAddress((void**)&h1, g_h1);
    cudaGetSymbolAddress((void**)&qb, g_q);
    cudaGetSymbolAddress((void**)&kb, g_k);
    cudaGetSymbolAddress((void**)&vb, g_v);

    const dim3 blk(256);
    const int RED_BLOCKS = (Bsz * Hd / 4) / 256;   // 512

    // 1) lin0: split-K=2 -> partials qb/kb -> reduce+bias -> h0  (256 CTAs)
    {
        GemmArgs a{};
        a.A = x; a.W[0] = lin0_w; a.C[0] = qb; a.C[1] = kb;
        a.M = Bsz; a.N = Hd; a.K = INd;
        gemm_kernel<2, 2><<<dim3(Hd / BN, Bsz / BM, 2), blk>>>(a);
        reduce_bias_kernel<<<RED_BLOCKS, 256>>>(qb, kb, lin0_b, h0);
    }

    // ---- block 1 (h0 -> h1) ----
    {
        GemmArgs a{};
        a.A = h0;
        a.W[0] = b1_qw; a.W[1] = b1_kw; a.W[2] = b1_vw;
        a.bias[0] = b1_qb; a.bias[1] = b1_kb; a.bias[2] = b1_vb;
        a.C[0] = qb; a.C[1] = kb; a.C[2] = vb;
        a.M = Bsz; a.N = Hd; a.K = Hd;
        gemm_kernel<0, 1><<<dim3(Hd / BN, Bsz / BM, 3), blk>>>(a);
    }
    attn_kernel<<<Bsz, 256>>>(qb, kb, vb, h0);
    {
        // f1: split-K=2 (q/k buffers free after attn) -> reduce(gelu+residual)
        GemmArgs a{};
        a.A = h0; a.W[0] = b1_f1w; a.C[0] = qb; a.C[1] = kb;
        a.M = Bsz; a.N = Hd; a.K = Hd;
        gemm_kernel<2, 2><<<dim3(Hd / BN, Bsz / BM, 2), blk>>>(a);
        reduce_gelu_kernel<<<RED_BLOCKS, 256>>>(qb, kb, b1_f1b, h0, h1);
    }

    // ---- block 2 (h1 -> h0) ----
    {
        GemmArgs a{};
        a.A = h1;
        a.W[0] = b2_qw; a.W[1] = b2_kw; a.W[2] = b2_vw;
        a.bias[0] = b2_qb; a.bias[1] = b2_kb; a.bias[2] = b2_vb;
        a.C[0] = qb; a.C[1] = kb; a.C[2] = vb;
        a.M = Bsz; a.N = Hd; a.K = Hd;
        gemm_kernel<0, 1><<<dim3(Hd / BN, Bsz / BM, 3), blk>>>(a);
    }
    attn_kernel<<<Bsz, 256>>>(qb, kb, vb, h1);
    {
        GemmArgs a{};
        a.A = h1; a.W[0] = b2_f1w; a.C[0] = qb; a.C[1] = kb;
        a.M = Bsz; a.N = Hd; a.K = Hd;
        gemm_kernel<2, 2><<<dim3(Hd / BN, Bsz / BM, 2), blk>>>(a);
        reduce_gelu_kernel<<<RED_BLOCKS, 256>>>(qb, kb, b2_f1b, h1, h0);
    }

    // 4) fea: split-K=4, partials packed in g_q (128 CTAs)
    {
        GemmArgs a{};
        a.A = h0; a.W[0] = fea_w;
        a.C[0] = qb;
        a.C[1] = qb + Bsz * Pd;
        a.C[2] = qb + 2 * Bsz * Pd;
        a.C[3] = qb + 3 * Bsz * Pd;
        a.M = Bsz; a.N = Pd; a.K = Hd;
        gemm_kernel<2, 4><<<dim3(Pd / BN, Bsz / BM, 4), blk>>>(a);
    }

    // 5) reduce partials + bias -> fea (d_out), then out[b] = fea·reg_w + reg_b
    fea_reg_kernel<<<Bsz, 128>>>(qb, fea_b, reg_w, reg_b, out_fea, out_scalar);
}

// round 11
// speedup vs baseline: 1.6750x; 1.3510x over previous
#include <cuda_runtime.h>
#include <cuda_bf16.h>
#include <math.h>
#include <stdint.h>

#define Bsz 1024
#define INd 256
#define Hd  512
#define Pd  128

// ---------------- scratch (no allocations allowed) ----------------
__device__ float g_h0[Bsz * Hd];
__device__ float g_h1[Bsz * Hd];
__device__ float g_q [Bsz * Hd];
__device__ float g_k [Bsz * Hd];
__device__ float g_v [Bsz * Hd];

// bf16 hi/lo buffers: 10 weight segments + x
#define OFF_LIN0 0
#define OFF_B1Q  131072
#define OFF_B1K  393216
#define OFF_B1V  655360
#define OFF_B1F  917504
#define OFF_B2Q  1179648
#define OFF_B2K  1441792
#define OFF_B2V  1703936
#define OFF_B2F  1966080
#define OFF_FEA  2228224
#define OFF_X    2293760
#define WTOT     2555904
__device__ __nv_bfloat16 g_wh[WTOT];
__device__ __nv_bfloat16 g_wl[WTOT];
__device__ __nv_bfloat16 g_pAh[Bsz * Hd];
__device__ __nv_bfloat16 g_pAl[Bsz * Hd];
__device__ __nv_bfloat16 g_pBh[Bsz * Hd];
__device__ __nv_bfloat16 g_pBl[Bsz * Hd];

// ---------------- helpers ----------------
__device__ __forceinline__ float ex2f(float x) {
    float y; asm("ex2.approx.f32 %0, %1;" : "=f"(y) : "f"(x)); return y;
}
__device__ __forceinline__ float gelu_exact(float t) {
    return 0.5f * t * (1.0f + erff(t * 0.70710678118654752f));
}
__device__ __forceinline__ uint32_t smem_to_u32(const void* p) {
    uint32_t a;
    asm("{ .reg .u64 t; cvta.to.shared.u64 t, %1; cvt.u32.u64 %0, t; }" : "=r"(a) : "l"(p));
    return a;
}
#define CP16(dst, src) \
    asm volatile("cp.async.cg.shared.global [%0], [%1], 16;" :: "r"(dst), "l"(src))
#define CP_COMMIT() asm volatile("cp.async.commit_group;" ::: "memory")
#define CP_WAIT0()  asm volatile("cp.async.wait_group 0;" ::: "memory")

// mma.sync m16n8k16 bf16 (sm_80+ PTX, no arch-suffix gating)
__device__ __forceinline__ void mma16816(float c[4], const uint32_t a[4], const uint32_t b[2]) {
    asm volatile(
        "mma.sync.aligned.m16n8k16.row.col.f32.bf16.bf16.f32 "
        "{%0,%1,%2,%3}, {%4,%5,%6,%7}, {%8,%9}, {%0,%1,%2,%3};"
        : "+f"(c[0]), "+f"(c[1]), "+f"(c[2]), "+f"(c[3])
        : "r"(a[0]), "r"(a[1]), "r"(a[2]), "r"(a[3]), "r"(b[0]), "r"(b[1]));
}

// ---------------- conversion kernel: f32 -> (hi,lo) bf16 ----------------
#define NSEG 11
struct ConvArgs { const float* src[NSEG]; int off[NSEG]; int n4[NSEG]; };

__global__ __launch_bounds__(256) void conv_kernel(ConvArgs a) {
    const int s = blockIdx.y;
    const float* __restrict__ src = a.src[s];
    __nv_bfloat16* __restrict__ hi = g_wh + a.off[s];
    __nv_bfloat16* __restrict__ lo = g_wl + a.off[s];
    const int n4 = a.n4[s];
    for (int i = blockIdx.x * 256 + threadIdx.x; i < n4; i += gridDim.x * 256) {
        float4 v = ((const float4*)src)[i];
        __nv_bfloat16 h0 = __float2bfloat16(v.x), h1 = __float2bfloat16(v.y);
        __nv_bfloat16 h2 = __float2bfloat16(v.z), h3 = __float2bfloat16(v.w);
        ((__nv_bfloat162*)hi)[i * 2]     = __nv_bfloat162(h0, h1);
        ((__nv_bfloat162*)hi)[i * 2 + 1] = __nv_bfloat162(h2, h3);
        ((__nv_bfloat162*)lo)[i * 2] = __nv_bfloat162(
            __float2bfloat16(v.x - __bfloat162float(h0)),
            __float2bfloat16(v.y - __bfloat162float(h1)));
        ((__nv_bfloat162*)lo)[i * 2 + 1] = __nv_bfloat162(
            __float2bfloat16(v.z - __bfloat162float(h2)),
            __float2bfloat16(v.w - __bfloat162float(h3)));
    }
}

// ---------------- tensor GEMM: C[1024,N] = A[1024,KD] @ W[N,KD]^T + bias ----------------
// bf16x3: acc += ah*wh + ah*wl + al*wh  (fp32 accumulate in HMMA)
// EPI: 0 = qkv (z selects W/bias/C), 1 = lin0 (+bf16 pair out),
//      2 = f1 (res + gelu, +bf16 pair out), 3 = fea (bias only)
struct TGemmArgs {
    const __nv_bfloat16 *a_hi, *a_lo;
    const __nv_bfloat16 *w_hi[3], *w_lo[3];
    const float* bias[3];
    const float* res;
    float* C[3];
    __nv_bfloat16 *o_hi, *o_lo;
    int N;
};

// smem: 4 matrices (Ah, Al, Wh, Wl), each 64 rows x 144 bytes (64 bf16 + 8 pad)
#define ROWB 144
#define MATB (64 * ROWB)   // 9216
#define SM_AH 0
#define SM_AL MATB
#define SM_WH (2 * MATB)
#define SM_WL (3 * MATB)

template <int EPI, int KD>
__global__ __launch_bounds__(128) void tgemm_kernel(TGemmArgs g) {
    __shared__ __align__(16) char smem[4 * MATB];   // 36,864 B < 48 KB
    const uint32_t sbase = smem_to_u32(smem);

    const int tid = threadIdx.x;
    const int wid = tid >> 5, lane = tid & 31;
    const int gid = lane >> 2, tig = lane & 3;
    const int warpRow = wid >> 1, warpCol = wid & 1;   // 2x2 warps, 32x32 each
    const int z = (EPI == 0) ? blockIdx.z : 0;
    const int n0 = blockIdx.x * 64;
    const int m0 = blockIdx.y * 64;
    const int N = g.N;
    const int Kb = KD * 2;   // row bytes in bf16 operand buffers

    const char* gA[2] = { (const char*)g.a_hi    + (size_t)m0 * Kb,
                          (const char*)g.a_lo    + (size_t)m0 * Kb };
    const char* gW[2] = { (const char*)g.w_hi[z] + (size_t)n0 * Kb,
                          (const char*)g.w_lo[z] + (size_t)n0 * Kb };

    float acc[2][4][4];
#pragma unroll
    for (int mt = 0; mt < 2; mt++)
#pragma unroll
        for (int nt = 0; nt < 4; nt++)
#pragma unroll
            for (int i = 0; i < 4; i++) acc[mt][nt][i] = 0.f;

    const int NCH = KD / 64;
    for (int c = 0; c < NCH; c++) {
        // stage chunk: each matrix = 64 rows x 128B = 512 16B-units, 4/thread
#pragma unroll
        for (int mat = 0; mat < 4; mat++) {
            const char* gp = (mat < 2) ? gA[mat] : gW[mat - 2];
#pragma unroll
            for (int i = 0; i < 4; i++) {
                int u = tid + i * 128;
                int row = u >> 3, cb = (u & 7) * 16;
                CP16(sbase + mat * MATB + row * ROWB + cb,
                     gp + (size_t)row * Kb + c * 128 + cb);
            }
        }
        CP_COMMIT();
        CP_WAIT0();
        __syncthreads();

#pragma unroll
        for (int ks = 0; ks < 4; ks++) {
            const int kb = ks * 32;   // 16 bf16 = 32 bytes
            uint32_t ah[2][4], al[2][4], wh[4][2], wl[4][2];
#pragma unroll
            for (int mt = 0; mt < 2; mt++) {
                int ro = (warpRow * 32 + mt * 16 + gid) * ROWB + kb + tig * 4;
                ah[mt][0] = *(const uint32_t*)(smem + SM_AH + ro);
                ah[mt][1] = *(const uint32_t*)(smem + SM_AH + ro + 8 * ROWB);
                ah[mt][2] = *(const uint32_t*)(smem + SM_AH + ro + 16);
                ah[mt][3] = *(const uint32_t*)(smem + SM_AH + ro + 8 * ROWB + 16);
                al[mt][0] = *(const uint32_t*)(smem + SM_AL + ro);
                al[mt][1] = *(const uint32_t*)(smem + SM_AL + ro + 8 * ROWB);
                al[mt][2] = *(const uint32_t*)(smem + SM_AL + ro + 16);
                al[mt][3] = *(const uint32_t*)(smem + SM_AL + ro + 8 * ROWB + 16);
            }
#pragma unroll
            for (int nt = 0; nt < 4; nt++) {
                int ro = (warpCol * 32 + nt * 8 + gid) * ROWB + kb + tig * 4;
                wh[nt][0] = *(const uint32_t*)(smem + SM_WH + ro);
                wh[nt][1] = *(const uint32_t*)(smem + SM_WH + ro + 16);
                wl[nt][0] = *(const uint32_t*)(smem + SM_WL + ro);
                wl[nt][1] = *(const uint32_t*)(smem + SM_WL + ro + 16);
            }
#pragma unroll
            for (int mt = 0; mt < 2; mt++)
#pragma unroll
                for (int nt = 0; nt < 4; nt++) {
                    mma16816(acc[mt][nt], ah[mt], wh[nt]);
                    mma16816(acc[mt][nt], ah[mt], wl[nt]);
                    mma16816(acc[mt][nt], al[mt], wh[nt]);
                }
        }
        __syncthreads();   // before next chunk overwrites smem
    }

    // epilogue: register fragments -> global
    const float* __restrict__ bias = g.bias[z];
    float* __restrict__ C = g.C[z];
#pragma unroll
    for (int mt = 0; mt < 2; mt++) {
        const int gm0 = m0 + warpRow * 32 + mt * 16 + gid;
        const int gm1 = gm0 + 8;
#pragma unroll
        for (int nt = 0; nt < 4; nt++) {
            const int gn = n0 + warpCol * 32 + nt * 8 + tig * 2;
            const float b0 = bias[gn], b1 = bias[gn + 1];
            float v00 = acc[mt][nt][0] + b0, v01 = acc[mt][nt][1] + b1;
            float v10 = acc[mt][nt][2] + b0, v11 = acc[mt][nt][3] + b1;
            if (EPI == 2) {
                const int i0 = gm0 * N + gn, i1 = gm1 * N + gn;
                float2 r0 = *(const float2*)&g.res[i0];
                float2 r1 = *(const float2*)&g.res[i1];
                v00 = r0.x + gelu_exact(v00); v01 = r0.y + gelu_exact(v01);
                v10 = r1.x + gelu_exact(v10); v11 = r1.y + gelu_exact(v11);
            }
            *(float2*)&C[gm0 * N + gn] = make_float2(v00, v01);
            *(float2*)&C[gm1 * N + gn] = make_float2(v10, v11);
            if (EPI == 1 || EPI == 2) {
                __nv_bfloat16 h00 = __float2bfloat16(v00), h01 = __float2bfloat16(v01);
                __nv_bfloat16 h10 = __float2bfloat16(v10), h11 = __float2bfloat16(v11);
                *(__nv_bfloat162*)&g.o_hi[gm0 * N + gn] = __nv_bfloat162(h00, h01);
                *(__nv_bfloat162*)&g.o_hi[gm1 * N + gn] = __nv_bfloat162(h10, h11);
                *(__nv_bfloat162*)&g.o_lo[gm0 * N + gn] = __nv_bfloat162(
                    __float2bfloat16(v00 - __bfloat162float(h00)),
                    __float2bfloat16(v01 - __bfloat162float(h01)));
                *(__nv_bfloat162*)&g.o_lo[gm1 * N + gn] = __nv_bfloat162(
                    __float2bfloat16(v10 - __bfloat162float(h10)),
                    __float2bfloat16(v11 - __bfloat162float(h11)));
            }
        }
    }
}

// ---------------- attention (MUFU floor; emits bf16 hi/lo of h) ----------------
__global__ __launch_bounds__(256) void attn_kernel(const float* __restrict__ q,
                                                   const float* __restrict__ k,
                                                   const float* __restrict__ v,
                                                   float* __restrict__ h,
                                                   __nv_bfloat16* __restrict__ oh,
                                                   __nv_bfloat16* __restrict__ ol) {
    const int b = blockIdx.x;
    __shared__ float k2s[Hd];
    __shared__ float vs[Hd];
    __shared__ float redmax[256];
    __shared__ float redmin[256];
    const int tid = threadIdx.x;
    const float LOG2E = 1.4426950408889634f;

    float lmax = -1e30f, lmin = 1e30f;
#pragma unroll
    for (int ii = 0; ii < Hd / 256; ii++) {
        int j = tid + ii * 256;
        float kk = k[b * Hd + j] * LOG2E;
        k2s[j] = kk;
        vs[j]  = v[b * Hd + j];
        lmax = fmaxf(lmax, kk);
        lmin = fminf(lmin, kk);
    }
    redmax[tid] = lmax;
    redmin[tid] = lmin;
    __syncthreads();
    for (int s = 128; s > 0; s >>= 1) {
        if (tid < s) {
            redmax[tid] = fmaxf(redmax[tid], redmax[tid + s]);
            redmin[tid] = fminf(redmin[tid], redmin[tid + s]);
        }
        __syncthreads();
    }
    const float kmax = redmax[0], kmin = redmin[0];

    const float q0 = q[b * Hd + tid];
    const float q1 = q[b * Hd + tid + 256];
    const float m0 = (q0 >= 0.f) ? q0 * kmax : q0 * kmin;
    const float m1 = (q1 >= 0.f) ? q1 * kmax : q1 * kmin;

    float d0 = 0.f, d1 = 0.f, n0 = 0.f, n1 = 0.f;
#pragma unroll 8
    for (int j = 0; j < Hd; j++) {
        float kv = k2s[j];
        float vv = vs[j];
        float e0 = ex2f(fmaf(q0, kv, -m0));
        float e1 = ex2f(fmaf(q1, kv, -m1));
        d0 += e0;
        d1 += e1;
        n0 = fmaf(e0, vv, n0);
        n1 = fmaf(e1, vv, n1);
    }
    int i0 = b * Hd + tid, i1 = i0 + 256;
    float r0 = h[i0] + n0 / d0;
    float r1 = h[i1] + n1 / d1;
    h[i0] = r0; h[i1] = r1;
    __nv_bfloat16 h0b = __float2bfloat16(r0);
    __nv_bfloat16 h1b = __float2bfloat16(r1);
    oh[i0] = h0b; ol[i0] = __float2bfloat16(r0 - __bfloat162float(h0b));
    oh[i1] = h1b; ol[i1] = __float2bfloat16(r1 - __bfloat162float(h1b));
}

// ---------------- reg head ----------------
__global__ __launch_bounds__(256) void reg_kernel(const float* __restrict__ fea,
                                                  const float* __restrict__ reg_w,
                                                  const float* __restrict__ reg_b,
                                                  float* __restrict__ out) {
    const int warp = (blockIdx.x * blockDim.x + threadIdx.x) >> 5;
    const int lane = threadIdx.x & 31;
    if (warp >= Bsz) return;
    float s = 0.f;
#pragma unroll
    for (int p = lane; p < Pd; p += 32)
        s = fmaf(fea[warp * Pd + p], reg_w[p], s);
#pragma unroll
    for (int o = 16; o; o >>= 1) s += __shfl_xor_sync(0xffffffffu, s, o);
    if (lane == 0) out[warp] = s + reg_b[0];
}

// ---------------- launcher ----------------
extern "C" void kernel_launch(void* const* d_in, const int* in_sizes, int n_in,
                              void* d_out, int out_size) {
    const float* x      = (const float*)d_in[0];
    const float* lin0_w = (const float*)d_in[1];
    const float* lin0_b = (const float*)d_in[2];
    const float* b1_qw = (const float*)d_in[3];  const float* b1_qb = (const float*)d_in[4];
    const float* b1_kw = (const float*)d_in[5];  const float* b1_kb = (const float*)d_in[6];
    const float* b1_vw = (const float*)d_in[7];  const float* b1_vb = (const float*)d_in[8];
    const float* b1_f1w = (const float*)d_in[9]; const float* b1_f1b = (const float*)d_in[10];
    const float* b2_qw = (const float*)d_in[11]; const float* b2_qb = (const float*)d_in[12];
    const float* b2_kw = (const float*)d_in[13]; const float* b2_kb = (const float*)d_in[14];
    const float* b2_vw = (const float*)d_in[15]; const float* b2_vb = (const float*)d_in[16];
    const float* b2_f1w = (const float*)d_in[17]; const float* b2_f1b = (const float*)d_in[18];
    const float* fea_w = (const float*)d_in[19]; const float* fea_b = (const float*)d_in[20];
    const float* reg_w = (const float*)d_in[21]; const float* reg_b = (const float*)d_in[22];

    float* out_scalar = (float*)d_out;           // [B]
    float* out_fea    = (float*)d_out + Bsz;     // [B, P]

    float *h0, *h1, *qb, *kb, *vb;
    __nv_bfloat16 *wh, *wl, *pAh, *pAl, *pBh, *pBl;
    cudaGetSymbolAddress((void**)&h0, g_h0);
    cudaGetSymbolAddress((void**)&h1, g_h1);
    cudaGetSymbolAddress((void**)&qb, g_q);
    cudaGetSymbolAddress((void**)&kb, g_k);
    cudaGetSymbolAddress((void**)&vb, g_v);
    cudaGetSymbolAddress((void**)&wh, g_wh);
    cudaGetSymbolAddress((void**)&wl, g_wl);
    cudaGetSymbolAddress((void**)&pAh, g_pAh);
    cudaGetSymbolAddress((void**)&pAl, g_pAl);
    cudaGetSymbolAddress((void**)&pBh, g_pBh);
    cudaGetSymbolAddress((void**)&pBl, g_pBl);

    // 0) convert all weights + x to bf16 hi/lo
    {
        ConvArgs a{};
        const float* srcs[NSEG] = {lin0_w, b1_qw, b1_kw, b1_vw, b1_f1w,
                                   b2_qw, b2_kw, b2_vw, b2_f1w, fea_w, x};
        const int offs[NSEG] = {OFF_LIN0, OFF_B1Q, OFF_B1K, OFF_B1V, OFF_B1F,
                                OFF_B2Q, OFF_B2K, OFF_B2V, OFF_B2F, OFF_FEA, OFF_X};
        const int ns[NSEG] = {Hd*INd, Hd*Hd, Hd*Hd, Hd*Hd, Hd*Hd,
                              Hd*Hd, Hd*Hd, Hd*Hd, Hd*Hd, Pd*Hd, Bsz*INd};
        for (int s = 0; s < NSEG; s++) { a.src[s] = srcs[s]; a.off[s] = offs[s]; a.n4[s] = ns[s] / 4; }
        conv_kernel<<<dim3(48, NSEG), 256>>>(a);
    }

    // 1) lin0: h0 = x @ lin0_w^T + b  (+ bf16 pair A)
    {
        TGemmArgs a{};
        a.a_hi = wh + OFF_X; a.a_lo = wl + OFF_X;
        a.w_hi[0] = wh + OFF_LIN0; a.w_lo[0] = wl + OFF_LIN0;
        a.bias[0] = lin0_b; a.C[0] = h0;
        a.o_hi = pAh; a.o_lo = pAl; a.N = Hd;
        tgemm_kernel<1, 256><<<dim3(8, 16, 1), 128>>>(a);
    }

    // ---- block 1 ----
    {
        TGemmArgs a{};
        a.a_hi = pAh; a.a_lo = pAl;
        a.w_hi[0] = wh + OFF_B1Q; a.w_lo[0] = wl + OFF_B1Q;
        a.w_hi[1] = wh + OFF_B1K; a.w_lo[1] = wl + OFF_B1K;
        a.w_hi[2] = wh + OFF_B1V; a.w_lo[2] = wl + OFF_B1V;
        a.bias[0] = b1_qb; a.bias[1] = b1_kb; a.bias[2] = b1_vb;
        a.C[0] = qb; a.C[1] = kb; a.C[2] = vb; a.N = Hd;
        tgemm_kernel<0, 512><<<dim3(8, 16, 3), 128>>>(a);
    }
    attn_kernel<<<Bsz, 256>>>(qb, kb, vb, h0, pAh, pAl);
    {
        TGemmArgs a{};
        a.a_hi = pAh; a.a_lo = pAl;
        a.w_hi[0] = wh + OFF_B1F; a.w_lo[0] = wl + OFF_B1F;
        a.bias[0] = b1_f1b; a.res = h0; a.C[0] = h1;
        a.o_hi = pBh; a.o_lo = pBl; a.N = Hd;
        tgemm_kernel<2, 512><<<dim3(8, 16, 1), 128>>>(a);
    }

    // ---- block 2 ----
    {
        TGemmArgs a{};
        a.a_hi = pBh; a.a_lo = pBl;
        a.w_hi[0] = wh + OFF_B2Q; a.w_lo[0] = wl + OFF_B2Q;
        a.w_hi[1] = wh + OFF_B2K; a.w_lo[1] = wl + OFF_B2K;
        a.w_hi[2] = wh + OFF_B2V; a.w_lo[2] = wl + OFF_B2V;
        a.bias[0] = b2_qb; a.bias[1] = b2_kb; a.bias[2] = b2_vb;
        a.C[0] = qb; a.C[1] = kb; a.C[2] = vb; a.N = Hd;
        tgemm_kernel<0, 512><<<dim3(8, 16, 3), 128>>>(a);
    }
    attn_kernel<<<Bsz, 256>>>(qb, kb, vb, h1, pBh, pBl);
    {
        TGemmArgs a{};
        a.a_hi = pBh; a.a_lo = pBl;
        a.w_hi[0] = wh + OFF_B2F; a.w_lo[0] = wl + OFF_B2F;
        a.bias[0] = b2_f1b; a.res = h1; a.C[0] = h0;
        a.o_hi = pAh; a.o_lo = pAl; a.N = Hd;
        tgemm_kernel<2, 512><<<dim3(8, 16, 1), 128>>>(a);
    }

    // 4) fea -> d_out directly
    {
        TGemmArgs a{};
        a.a_hi = pAh; a.a_lo = pAl;
        a.w_hi[0] = wh + OFF_FEA; a.w_lo[0] = wl + OFF_FEA;
        a.bias[0] = fea_b; a.C[0] = out_fea; a.N = Pd;
        tgemm_kernel<3, 512><<<dim3(2, 16, 1), 128>>>(a);
    }

    // 5) out[b] = fea·reg_w + reg_b
    reg_kernel<<<(Bsz * 32) / 256, 256>>>(out_fea, reg_w, reg_b, out_scalar);
}